// round 1
// baseline (speedup 1.0000x reference)
#include <cuda_runtime.h>
#include <cuda_bf16.h>

// Problem constants (fixed-shape benchmark)
constexpr int B    = 8;
constexpr int HQ   = 32;
constexpr int HKV  = 8;
constexpr int G    = 4;      // HQ / HKV
constexpr int D    = 128;
constexpr int BS   = 128;    // page size
constexpr int NCMPB = 16;    // max compressed blocks per batch
constexpr int NORIB = 64;    // max original blocks per batch
constexpr int NSPLIT = 16;   // one CTA per compressed page
constexpr int PAGE_ELEMS = 2 * BS * HKV * D;   // 262144 floats per page
constexpr float SCALE  = 0.08838834764831845f; // 1/sqrt(128)
constexpr float NEGINF = -1e30f;

// Scratch: partial flash-decoding state (allocation-free __device__ globals)
__device__ float g_pacc[B * HKV * NSPLIT * G * D];  // 2 MB
__device__ float g_pm  [B * HKV * NSPLIT * G];
__device__ float g_ps  [B * HKV * NSPLIT * G];

__device__ __forceinline__ float warp_sum(float v) {
    v += __shfl_xor_sync(0xffffffffu, v, 16);
    v += __shfl_xor_sync(0xffffffffu, v, 8);
    v += __shfl_xor_sync(0xffffffffu, v, 4);
    v += __shfl_xor_sync(0xffffffffu, v, 2);
    v += __shfl_xor_sync(0xffffffffu, v, 1);
    return v;
}

// ---------------------------------------------------------------------------
// Kernel 1: per-(b, hkv, split) partial attention over one compressed page.
// 256 threads = 8 warps; warp-per-token, float4 per lane (fully coalesced).
// ---------------------------------------------------------------------------
__global__ __launch_bounds__(256) void split_kernel(
    const float* __restrict__ q,
    const float* __restrict__ cmp_kv,
    const int*   __restrict__ cmp_bt,
    const int*   __restrict__ seqused)
{
    const int split = blockIdx.x % NSPLIT;
    const int bh    = blockIdx.x / NSPLIT;
    const int hkv   = bh % HKV;
    const int b     = bh / HKV;
    const int tid   = threadIdx.x;
    const int w     = tid >> 5;
    const int l     = tid & 31;

    const int seq     = seqused[b];
    const int cmp_len = seq >> 2;
    const int start   = split * BS;
    int cnt = cmp_len - start;
    if (cnt > BS) cnt = BS;

    const int pmbase = ((b * HKV + hkv) * NSPLIT + split) * G;
    if (cnt <= 0) {
        if (tid < G) { g_pm[pmbase + tid] = NEGINF; g_ps[pmbase + tid] = 0.f; }
        return;
    }

    const int page = cmp_bt[b * NCMPB + split];
    const float4* kbase = (const float4*)(cmp_kv + (size_t)page * PAGE_ELEMS + hkv * D);
    const float4* vbase = kbase + (BS * HKV * D) / 4;   // V plane of the page
    constexpr int TOKSTRIDE = HKV * D / 4;              // 256 float4 between tokens

    // Load q for the 4 GQA heads of this kv head (float4 per lane)
    float4 qv[G];
    const float* qb = q + ((size_t)b * HQ + hkv * G) * D;
#pragma unroll
    for (int g = 0; g < G; ++g)
        qv[g] = ((const float4*)(qb + g * D))[l];

    float  m[G], s[G];
    float4 acc[G];
#pragma unroll
    for (int g = 0; g < G; ++g) {
        m[g] = NEGINF; s[g] = 0.f;
        acc[g] = make_float4(0.f, 0.f, 0.f, 0.f);
    }

    for (int t = w; t < cnt; t += 8) {
        const float4 k4 = kbase[(size_t)t * TOKSTRIDE + l];
        const float4 v4 = vbase[(size_t)t * TOKSTRIDE + l];
#pragma unroll
        for (int g = 0; g < G; ++g) {
            float x = qv[g].x * k4.x + qv[g].y * k4.y + qv[g].z * k4.z + qv[g].w * k4.w;
            x = warp_sum(x) * SCALE;
            const float nm = fmaxf(m[g], x);
            const float c  = __expf(m[g] - nm);
            const float p  = __expf(x    - nm);
            s[g] = s[g] * c + p;
            acc[g].x = acc[g].x * c + p * v4.x;
            acc[g].y = acc[g].y * c + p * v4.y;
            acc[g].z = acc[g].z * c + p * v4.z;
            acc[g].w = acc[g].w * c + p * v4.w;
            m[g] = nm;
        }
    }

    // CTA combine across 8 warps
    __shared__ float sm_m[8][G], sm_s[8][G];
    __shared__ float sm_acc[8][G][D];     // 16 KB
    __shared__ float sm_M[G];

    if (l == 0) {
#pragma unroll
        for (int g = 0; g < G; ++g) { sm_m[w][g] = m[g]; sm_s[w][g] = s[g]; }
    }
#pragma unroll
    for (int g = 0; g < G; ++g)
        ((float4*)sm_acc[w][g])[l] = acc[g];
    __syncthreads();

    if (tid < G) {
        const int g = tid;
        float M = NEGINF;
#pragma unroll
        for (int ww = 0; ww < 8; ++ww) M = fmaxf(M, sm_m[ww][g]);
        float S = 0.f;
#pragma unroll
        for (int ww = 0; ww < 8; ++ww) S += __expf(sm_m[ww][g] - M) * sm_s[ww][g];
        sm_M[g] = M;
        g_pm[pmbase + g] = M;
        g_ps[pmbase + g] = S;
    }
    __syncthreads();

    float* outp = g_pacc + (size_t)pmbase * D;
    for (int idx = tid; idx < G * D; idx += 256) {
        const int g = idx / D, d = idx % D;
        const float M = sm_M[g];
        float v = 0.f;
#pragma unroll
        for (int ww = 0; ww < 8; ++ww)
            v += __expf(sm_m[ww][g] - M) * sm_acc[ww][g][d];
        outp[idx] = v;
    }
}

// ---------------------------------------------------------------------------
// Kernel 2: per-(b, hkv) merge of split partials + original-cache tail (<=3
// tokens) + sink logit. 128 threads, thread-per-d.
// ---------------------------------------------------------------------------
__global__ __launch_bounds__(128) void reduce_kernel(
    const float* __restrict__ q,
    const float* __restrict__ ori_kv,
    const float* __restrict__ sinks,
    const int*   __restrict__ ori_bt,
    const int*   __restrict__ seqused,
    float*       __restrict__ out)
{
    const int hkv = blockIdx.x % HKV;
    const int b   = blockIdx.x / HKV;
    const int tid = threadIdx.x;   // d index
    const int w   = tid >> 5;
    const int l   = tid & 31;

    const int seq      = seqused[b];
    const int cmp_len  = seq >> 2;
    const int cmp_base = cmp_len << 2;
    const int ntail    = seq - cmp_base;    // 0..3

    const float* qb = q + ((size_t)b * HQ + hkv * G) * D;

    __shared__ float sm_red[4][G];
    __shared__ float tl[3][G];
    float tv[3];

#pragma unroll
    for (int t = 0; t < 3; ++t) {
        if (t < ntail) {
            const int pos  = cmp_base + t;
            const int page = ori_bt[b * NORIB + (pos >> 7)];
            const float* kp = ori_kv + (size_t)page * PAGE_ELEMS
                              + (size_t)(pos & 127) * HKV * D + hkv * D;
            const float* vp = kp + BS * HKV * D;
            const float kd = kp[tid];
            tv[t] = vp[tid];
#pragma unroll
            for (int g = 0; g < G; ++g) {
                float x = qb[g * D + tid] * kd;
                x = warp_sum(x);
                if (l == 0) sm_red[w][g] = x;
            }
            __syncthreads();
            if (tid < G)
                tl[t][tid] = (sm_red[0][tid] + sm_red[1][tid]
                            + sm_red[2][tid] + sm_red[3][tid]) * SCALE;
            __syncthreads();
        }
    }

    const int   base = ((b * HKV + hkv) * NSPLIT) * G;
    const float* pacc = g_pacc + (size_t)base * D;

#pragma unroll
    for (int g = 0; g < G; ++g) {
        const float sink = sinks[hkv * G + g];
        float M = sink;
#pragma unroll
        for (int sp = 0; sp < NSPLIT; ++sp)
            M = fmaxf(M, g_pm[base + sp * G + g]);
#pragma unroll
        for (int t = 0; t < 3; ++t)
            if (t < ntail) M = fmaxf(M, tl[t][g]);

        float S   = __expf(sink - M);
        float num = 0.f;
#pragma unroll
        for (int sp = 0; sp < NSPLIT; ++sp) {
            const float wgt = __expf(g_pm[base + sp * G + g] - M);
            S   += wgt * g_ps[base + sp * G + g];
            num += wgt * pacc[(size_t)(sp * G + g) * D + tid];
        }
#pragma unroll
        for (int t = 0; t < 3; ++t) {
            if (t < ntail) {
                const float p = __expf(tl[t][g] - M);
                S   += p;
                num += p * tv[t];
            }
        }
        out[((size_t)b * HQ + hkv * G + g) * D + tid] = num / S;
    }
}

extern "C" void kernel_launch(void* const* d_in, const int* in_sizes, int n_in,
                              void* d_out, int out_size) {
    const float* q       = (const float*)d_in[0];
    const float* cmp_kv  = (const float*)d_in[1];
    const float* sinks   = (const float*)d_in[2];
    const int*   cmp_bt  = (const int*)d_in[3];
    const int*   seqused = (const int*)d_in[4];
    const float* ori_kv  = (const float*)d_in[5];
    const int*   ori_bt  = (const int*)d_in[6];
    // d_in[7] = cmp_ratio (compile-time constant 4 here)
    float* out = (float*)d_out;

    split_kernel<<<B * HKV * NSPLIT, 256>>>(q, cmp_kv, cmp_bt, seqused);
    reduce_kernel<<<B * HKV, 128>>>(q, ori_kv, sinks, ori_bt, seqused, out);
}

// round 2
// speedup vs baseline: 1.1417x; 1.1417x over previous
#include <cuda_runtime.h>
#include <cuda_bf16.h>

constexpr int B     = 8;
constexpr int HQ    = 32;
constexpr int HKV   = 8;
constexpr int G     = 4;
constexpr int D     = 128;
constexpr int BS    = 128;
constexpr int NCMPB = 16;
constexpr int NORIB = 64;
constexpr int NSPLIT = 16;
constexpr int PAGE_ELEMS = 2 * BS * HKV * D;
constexpr float SCALE  = 0.08838834764831845f;
constexpr float NEGINF = -1e30f;

__device__ float g_pacc[B * HKV * NSPLIT * G * D];  // 2 MB, unnormalized partial sums
__device__ float g_pm  [B * HKV * NSPLIT * G];      // per-split max
__device__ float g_ps  [B * HKV * NSPLIT * G];      // per-split exp-sum

__device__ __forceinline__ float warp_sum(float v) {
    v += __shfl_xor_sync(0xffffffffu, v, 16);
    v += __shfl_xor_sync(0xffffffffu, v, 8);
    v += __shfl_xor_sync(0xffffffffu, v, 4);
    v += __shfl_xor_sync(0xffffffffu, v, 2);
    v += __shfl_xor_sync(0xffffffffu, v, 1);
    return v;
}
__device__ __forceinline__ float warp_max(float v) {
    v = fmaxf(v, __shfl_xor_sync(0xffffffffu, v, 16));
    v = fmaxf(v, __shfl_xor_sync(0xffffffffu, v, 8));
    v = fmaxf(v, __shfl_xor_sync(0xffffffffu, v, 4));
    v = fmaxf(v, __shfl_xor_sync(0xffffffffu, v, 2));
    v = fmaxf(v, __shfl_xor_sync(0xffffffffu, v, 1));
    return v;
}

// ---------------------------------------------------------------------------
// Kernel 1: one CTA per (b, hkv, page). Two-pass:
//   pass 1: stream K  -> raw logits in SMEM (no exp in the load chain)
//   block step: per-g max/sum, store p = exp(logit - M) in place
//   pass 2: stream V  -> acc += p * v  (pure FMA, no rescale)
// ---------------------------------------------------------------------------
__global__ __launch_bounds__(256) void split_kernel(
    const float* __restrict__ q,
    const float* __restrict__ cmp_kv,
    const int*   __restrict__ cmp_bt,
    const int*   __restrict__ seqused)
{
    const int split = blockIdx.x % NSPLIT;
    const int bh    = blockIdx.x / NSPLIT;
    const int hkv   = bh % HKV;
    const int b     = bh / HKV;
    const int tid   = threadIdx.x;
    const int w     = tid >> 5;
    const int l     = tid & 31;

    const int seq     = seqused[b];
    const int cmp_len = seq >> 2;
    int cnt = cmp_len - split * BS;
    if (cnt > BS) cnt = BS;

    const int pmbase = ((b * HKV + hkv) * NSPLIT + split) * G;
    if (cnt <= 0) {
        if (tid < G) { g_pm[pmbase + tid] = NEGINF; g_ps[pmbase + tid] = 0.f; }
        return;
    }

    const int page = cmp_bt[b * NCMPB + split];
    const float4* kbase = (const float4*)(cmp_kv + (size_t)page * PAGE_ELEMS + hkv * D);
    const float4* vbase = kbase + (BS * HKV * D) / 4;
    constexpr int TOKSTRIDE = HKV * D / 4;

    float4 qv[G];
    const float* qb = q + ((size_t)b * HQ + hkv * G) * D;
#pragma unroll
    for (int g = 0; g < G; ++g)
        qv[g] = ((const float4*)(qb + g * D))[l];

    __shared__ float sm_p[G][BS + 4];     // raw logits, then probabilities
    __shared__ float sm_acc[8][G][D];     // 16 KB combine buffer

    // ---- pass 1: K -> logits ----
    if (cnt == BS) {
#pragma unroll
        for (int i = 0; i < BS / 8; ++i) {
            const int t = w + i * 8;
            const float4 k4 = kbase[(size_t)t * TOKSTRIDE + l];
#pragma unroll
            for (int g = 0; g < G; ++g) {
                float x = qv[g].x * k4.x + qv[g].y * k4.y + qv[g].z * k4.z + qv[g].w * k4.w;
                x = warp_sum(x);
                if (l == g) sm_p[g][t] = x * SCALE;
            }
        }
    } else {
        for (int t = w; t < cnt; t += 8) {
            const float4 k4 = kbase[(size_t)t * TOKSTRIDE + l];
#pragma unroll
            for (int g = 0; g < G; ++g) {
                float x = qv[g].x * k4.x + qv[g].y * k4.y + qv[g].z * k4.z + qv[g].w * k4.w;
                x = warp_sum(x);
                if (l == g) sm_p[g][t] = x * SCALE;
            }
        }
    }
    __syncthreads();

    // ---- block step: per-g max / sum, exp in place (warp g handles head g) ----
    if (w < G) {
        float vals[4];
        float mx = NEGINF;
#pragma unroll
        for (int i = 0; i < 4; ++i) {
            const int t = l + i * 32;
            vals[i] = (t < cnt) ? sm_p[w][t] : NEGINF;
            mx = fmaxf(mx, vals[i]);
        }
        mx = warp_max(mx);
        float s = 0.f;
#pragma unroll
        for (int i = 0; i < 4; ++i) {
            const int t = l + i * 32;
            if (t < cnt) {
                const float p = __expf(vals[i] - mx);
                s += p;
                sm_p[w][t] = p;
            }
        }
        s = warp_sum(s);
        if (l == 0) {
            g_pm[pmbase + w] = mx;
            g_ps[pmbase + w] = s;
        }
    }
    __syncthreads();

    // ---- pass 2: V -> acc (pure FMA) ----
    float4 acc[G];
#pragma unroll
    for (int g = 0; g < G; ++g) acc[g] = make_float4(0.f, 0.f, 0.f, 0.f);

    if (cnt == BS) {
#pragma unroll
        for (int i = 0; i < BS / 8; ++i) {
            const int t = w + i * 8;
            const float4 v4 = vbase[(size_t)t * TOKSTRIDE + l];
#pragma unroll
            for (int g = 0; g < G; ++g) {
                const float p = sm_p[g][t];
                acc[g].x += p * v4.x; acc[g].y += p * v4.y;
                acc[g].z += p * v4.z; acc[g].w += p * v4.w;
            }
        }
    } else {
        for (int t = w; t < cnt; t += 8) {
            const float4 v4 = vbase[(size_t)t * TOKSTRIDE + l];
#pragma unroll
            for (int g = 0; g < G; ++g) {
                const float p = sm_p[g][t];
                acc[g].x += p * v4.x; acc[g].y += p * v4.y;
                acc[g].z += p * v4.z; acc[g].w += p * v4.w;
            }
        }
    }

    // ---- combine 8 warps (shared max M, plain sum) ----
#pragma unroll
    for (int g = 0; g < G; ++g)
        ((float4*)sm_acc[w][g])[l] = acc[g];
    __syncthreads();

    float* outp = g_pacc + (size_t)pmbase * D;
    for (int idx = tid; idx < G * D; idx += 256) {
        const int g = idx >> 7, d = idx & 127;
        float v = 0.f;
#pragma unroll
        for (int ww = 0; ww < 8; ++ww) v += sm_acc[ww][g][d];
        outp[idx] = v;
    }
}

// ---------------------------------------------------------------------------
// Kernel 2: one CTA per (b, h) output head. 128 threads (thread = d).
// wgt precomputed -> 16 independent unrolled pacc loads. Tail (<=3 ori
// tokens) + sink folded in.
// ---------------------------------------------------------------------------
__global__ __launch_bounds__(128) void reduce_kernel(
    const float* __restrict__ q,
    const float* __restrict__ ori_kv,
    const float* __restrict__ sinks,
    const int*   __restrict__ ori_bt,
    const int*   __restrict__ seqused,
    float*       __restrict__ out)
{
    const int h   = blockIdx.x % HQ;
    const int b   = blockIdx.x / HQ;
    const int hkv = h >> 2;
    const int tid = threadIdx.x;
    const int w   = tid >> 5;
    const int l   = tid & 31;

    const int seq      = seqused[b];
    const int cmp_len  = seq >> 2;
    const int cmp_base = cmp_len << 2;
    const int ntail    = seq - cmp_base;   // 0..3

    const float qd = q[((size_t)b * HQ + h) * D + tid];

    __shared__ float sm_red[4];
    __shared__ float sm_bcast[3];
    float tl[3], tv[3];

#pragma unroll
    for (int t = 0; t < 3; ++t) {
        tl[t] = NEGINF; tv[t] = 0.f;
        if (t < ntail) {
            const int pos  = cmp_base + t;
            const int page = ori_bt[b * NORIB + (pos >> 7)];
            const float* kp = ori_kv + (size_t)page * PAGE_ELEMS
                              + (size_t)(pos & 127) * HKV * D + hkv * D;
            tv[t] = kp[BS * HKV * D + tid];
            float x = qd * kp[tid];
            x = warp_sum(x);
            if (l == 0) sm_red[w] = x;
            __syncthreads();
            if (tid == 0)
                sm_bcast[t] = (sm_red[0] + sm_red[1] + sm_red[2] + sm_red[3]) * SCALE;
            __syncthreads();
            tl[t] = sm_bcast[t];
        }
    }

    const int base = ((b * HKV + hkv) * NSPLIT) * G + (h & 3);

    float pm[NSPLIT];
#pragma unroll
    for (int sp = 0; sp < NSPLIT; ++sp) pm[sp] = g_pm[base + sp * G];

    const float sink = sinks[h];
    float M = sink;
#pragma unroll
    for (int sp = 0; sp < NSPLIT; ++sp) M = fmaxf(M, pm[sp]);
#pragma unroll
    for (int t = 0; t < 3; ++t) M = fmaxf(M, tl[t]);

    float wgt[NSPLIT];
    float S = __expf(sink - M);
#pragma unroll
    for (int sp = 0; sp < NSPLIT; ++sp) {
        wgt[sp] = __expf(pm[sp] - M);
        S += wgt[sp] * g_ps[base + sp * G];
    }

    const float* pacc = g_pacc + (size_t)base * D + tid;
    float num = 0.f;
#pragma unroll
    for (int sp = 0; sp < NSPLIT; ++sp) {
        if (wgt[sp] > 0.f)
            num += wgt[sp] * pacc[(size_t)sp * G * D];
    }
#pragma unroll
    for (int t = 0; t < 3; ++t) {
        if (t < ntail) {
            const float p = __expf(tl[t] - M);
            S   += p;
            num += p * tv[t];
        }
    }
    out[((size_t)b * HQ + h) * D + tid] = num / S;
}

extern "C" void kernel_launch(void* const* d_in, const int* in_sizes, int n_in,
                              void* d_out, int out_size) {
    const float* q       = (const float*)d_in[0];
    const float* cmp_kv  = (const float*)d_in[1];
    const float* sinks   = (const float*)d_in[2];
    const int*   cmp_bt  = (const int*)d_in[3];
    const int*   seqused = (const int*)d_in[4];
    const float* ori_kv  = (const float*)d_in[5];
    const int*   ori_bt  = (const int*)d_in[6];
    float* out = (float*)d_out;

    split_kernel<<<B * HKV * NSPLIT, 256>>>(q, cmp_kv, cmp_bt, seqused);
    reduce_kernel<<<B * HQ, 128>>>(q, ori_kv, sinks, ori_bt, seqused, out);
}

// round 4
// speedup vs baseline: 1.1511x; 1.0083x over previous
#include <cuda_runtime.h>
#include <cuda_bf16.h>

constexpr int B     = 8;
constexpr int HQ    = 32;
constexpr int HKV   = 8;
constexpr int G     = 4;
constexpr int D     = 128;
constexpr int BS    = 128;
constexpr int NCMPB = 16;
constexpr int NORIB = 64;
constexpr int NSPLIT = 16;
constexpr int PAGE_ELEMS = 2 * BS * HKV * D;
constexpr float SCALE  = 0.08838834764831845f;
constexpr float NEGINF = -1e30f;

// Allocation-free scratch (float4 where vector-accessed -> guaranteed 16B align)
__device__ float  g_pacc[B * HKV * NSPLIT * G * D];  // 2 MB unnormalized partials
__device__ float  g_pm  [B * HKV * NSPLIT * G];
__device__ float  g_ps  [B * HKV * NSPLIT * G];
__device__ float  g_tl  [B * HKV * 3 * G];           // tail logits
__device__ float4 g_tv  [B * HKV * 3 * (D / 4)];     // tail V rows (vectorized)
__device__ int    g_cnt [B * HKV];                   // arrival counters (zero-init)

__device__ __forceinline__ float warp_sum(float v) {
    v += __shfl_xor_sync(0xffffffffu, v, 16);
    v += __shfl_xor_sync(0xffffffffu, v, 8);
    v += __shfl_xor_sync(0xffffffffu, v, 4);
    v += __shfl_xor_sync(0xffffffffu, v, 2);
    v += __shfl_xor_sync(0xffffffffu, v, 1);
    return v;
}
__device__ __forceinline__ float warp_max(float v) {
    v = fmaxf(v, __shfl_xor_sync(0xffffffffu, v, 16));
    v = fmaxf(v, __shfl_xor_sync(0xffffffffu, v, 8));
    v = fmaxf(v, __shfl_xor_sync(0xffffffffu, v, 4));
    v = fmaxf(v, __shfl_xor_sync(0xffffffffu, v, 2));
    v = fmaxf(v, __shfl_xor_sync(0xffffffffu, v, 1));
    return v;
}

// Merge: run by the last-arriving split CTA of (b, hkv). 256 threads handle
// G*D = 512 outputs (2 per thread). All inputs are L2-hot (just written).
__device__ __forceinline__ void merge_bh(int bh, int hkv,
    const float* __restrict__ sinks, float* __restrict__ out)
{
    const int tid  = threadIdx.x;
    const int base = bh * NSPLIT * G;
    const int b    = bh / HKV;

#pragma unroll
    for (int rep = 0; rep < 2; ++rep) {
        const int idx = rep * 256 + tid;          // 0..511
        const int g = idx >> 7, d = idx & 127;    // warp-uniform g

        float pm[NSPLIT];
#pragma unroll
        for (int sp = 0; sp < NSPLIT; ++sp)
            pm[sp] = __ldcg(&g_pm[base + sp * G + g]);

        float tl[3];
#pragma unroll
        for (int t = 0; t < 3; ++t)
            tl[t] = __ldcg(&g_tl[(bh * 3 + t) * G + g]);

        const float sink = sinks[hkv * G + g];
        float M = sink;
#pragma unroll
        for (int sp = 0; sp < NSPLIT; ++sp) M = fmaxf(M, pm[sp]);
#pragma unroll
        for (int t = 0; t < 3; ++t) M = fmaxf(M, tl[t]);

        float S = __expf(sink - M);
        float num = 0.f;
#pragma unroll
        for (int sp = 0; sp < NSPLIT; ++sp) {
            const float w = __expf(pm[sp] - M);
            S += w * __ldcg(&g_ps[base + sp * G + g]);
            if (w > 0.f)
                num += w * __ldcg(&g_pacc[(size_t)(base + sp * G + g) * D + d]);
        }
        const float* tvf = (const float*)&g_tv[bh * 3 * (D / 4)];
#pragma unroll
        for (int t = 0; t < 3; ++t) {
            const float p = __expf(tl[t] - M);   // exactly 0 for invalid tail
            S   += p;
            num += p * tvf[t * D + d];
        }
        out[((size_t)b * HQ + hkv * G + g) * D + d] = num / S;
    }
}

// ---------------------------------------------------------------------------
// One CTA per (b, hkv, page). Two-pass flash partial + fused last-CTA merge.
// ---------------------------------------------------------------------------
__global__ __launch_bounds__(256) void attn_kernel(
    const float* __restrict__ q,
    const float* __restrict__ cmp_kv,
    const int*   __restrict__ cmp_bt,
    const int*   __restrict__ seqused,
    const float* __restrict__ ori_kv,
    const int*   __restrict__ ori_bt,
    const float* __restrict__ sinks,
    float*       __restrict__ out)
{
    const int split = blockIdx.x % NSPLIT;
    const int bh    = blockIdx.x / NSPLIT;
    const int hkv   = bh % HKV;
    const int b     = bh / HKV;
    const int tid   = threadIdx.x;
    const int w     = tid >> 5;
    const int l     = tid & 31;

    const int seq     = seqused[b];
    const int cmp_len = seq >> 2;
    int cnt = cmp_len - split * BS;
    if (cnt > BS) cnt = BS;

    const int pmbase = (bh * NSPLIT + split) * G;

    if (cnt <= 0) {
        if (tid < G) { g_pm[pmbase + tid] = NEGINF; g_ps[pmbase + tid] = 0.f; }
    } else {
        const int page = cmp_bt[b * NCMPB + split];
        const float4* kbase = (const float4*)(cmp_kv + (size_t)page * PAGE_ELEMS + hkv * D);
        const float4* vbase = kbase + (BS * HKV * D) / 4;
        constexpr int TOKSTRIDE = HKV * D / 4;

        float4 qv[G];
        const float* qb = q + ((size_t)b * HQ + hkv * G) * D;
#pragma unroll
        for (int g = 0; g < G; ++g)
            qv[g] = ((const float4*)(qb + g * D))[l];

        __shared__ __align__(16) float sm_p[G][BS + 4];
        __shared__ __align__(16) float sm_acc[8][G][D];

        // ---- pass 1: K -> raw logits ----
        if (cnt == BS) {
#pragma unroll
            for (int i = 0; i < BS / 8; ++i) {
                const int t = w + i * 8;
                const float4 k4 = kbase[(size_t)t * TOKSTRIDE + l];
#pragma unroll
                for (int g = 0; g < G; ++g) {
                    float x = qv[g].x * k4.x + qv[g].y * k4.y + qv[g].z * k4.z + qv[g].w * k4.w;
                    x = warp_sum(x);
                    if (l == g) sm_p[g][t] = x * SCALE;
                }
            }
        } else {
            for (int t = w; t < cnt; t += 8) {
                const float4 k4 = kbase[(size_t)t * TOKSTRIDE + l];
#pragma unroll
                for (int g = 0; g < G; ++g) {
                    float x = qv[g].x * k4.x + qv[g].y * k4.y + qv[g].z * k4.z + qv[g].w * k4.w;
                    x = warp_sum(x);
                    if (l == g) sm_p[g][t] = x * SCALE;
                }
            }
        }
        __syncthreads();

        // ---- block softmax numerators (warp g owns head g) ----
        if (w < G) {
            float vals[4];
            float mx = NEGINF;
#pragma unroll
            for (int i = 0; i < 4; ++i) {
                const int t = l + i * 32;
                vals[i] = (t < cnt) ? sm_p[w][t] : NEGINF;
                mx = fmaxf(mx, vals[i]);
            }
            mx = warp_max(mx);
            float s = 0.f;
#pragma unroll
            for (int i = 0; i < 4; ++i) {
                const int t = l + i * 32;
                if (t < cnt) {
                    const float p = __expf(vals[i] - mx);
                    s += p;
                    sm_p[w][t] = p;
                }
            }
            s = warp_sum(s);
            if (l == 0) { g_pm[pmbase + w] = mx; g_ps[pmbase + w] = s; }
        }
        __syncthreads();

        // ---- pass 2: V -> acc ----
        float4 acc[G];
#pragma unroll
        for (int g = 0; g < G; ++g) acc[g] = make_float4(0.f, 0.f, 0.f, 0.f);

        if (cnt == BS) {
#pragma unroll
            for (int i = 0; i < BS / 8; ++i) {
                const int t = w + i * 8;
                const float4 v4 = vbase[(size_t)t * TOKSTRIDE + l];
#pragma unroll
                for (int g = 0; g < G; ++g) {
                    const float p = sm_p[g][t];
                    acc[g].x += p * v4.x; acc[g].y += p * v4.y;
                    acc[g].z += p * v4.z; acc[g].w += p * v4.w;
                }
            }
        } else {
            for (int t = w; t < cnt; t += 8) {
                const float4 v4 = vbase[(size_t)t * TOKSTRIDE + l];
#pragma unroll
                for (int g = 0; g < G; ++g) {
                    const float p = sm_p[g][t];
                    acc[g].x += p * v4.x; acc[g].y += p * v4.y;
                    acc[g].z += p * v4.z; acc[g].w += p * v4.w;
                }
            }
        }

#pragma unroll
        for (int g = 0; g < G; ++g)
            ((float4*)sm_acc[w][g])[l] = acc[g];
        __syncthreads();

        float* outp = g_pacc + (size_t)pmbase * D;
        for (int idx = tid; idx < G * D; idx += 256) {
            const int g = idx >> 7, d = idx & 127;
            float v = 0.f;
#pragma unroll
            for (int ww = 0; ww < 8; ++ww) v += sm_acc[ww][g][d];
            outp[idx] = v;
        }

        // ---- split 0 also computes the <=3-token original-cache tail ----
        if (split == 0 && w < 3) {
            const int cmp_base = cmp_len << 2;
            const int ntail    = seq - cmp_base;     // 0..3
            float4* tvrow = &g_tv[(bh * 3 + w) * (D / 4)];
            if (w < ntail) {
                const int pos  = cmp_base + w;
                const int opage = ori_bt[b * NORIB + (pos >> 7)];
                const float* kp = ori_kv + (size_t)opage * PAGE_ELEMS
                                  + (size_t)(pos & 127) * HKV * D + hkv * D;
                const float4 k4 = ((const float4*)kp)[l];
                const float4 v4 = ((const float4*)(kp + BS * HKV * D))[l];
                tvrow[l] = v4;
#pragma unroll
                for (int g = 0; g < G; ++g) {
                    float x = qv[g].x * k4.x + qv[g].y * k4.y + qv[g].z * k4.z + qv[g].w * k4.w;
                    x = warp_sum(x);
                    if (l == g) g_tl[(bh * 3 + w) * G + g] = x * SCALE;
                }
            } else {
                if (l < G) g_tl[(bh * 3 + w) * G + l] = NEGINF;
                tvrow[l] = make_float4(0.f, 0.f, 0.f, 0.f);
            }
        }
    }

    // ---- last-CTA merge (threadFenceReduction pattern) ----
    __shared__ int s_last;
    __threadfence();
    if (tid == 0) {
        const int v = atomicAdd(&g_cnt[bh], 1);
        const int last = (v == NSPLIT - 1);
        if (last) g_cnt[bh] = 0;     // reset for next graph replay
        s_last = last;
    }
    __syncthreads();
    if (s_last) {
        __threadfence();
        merge_bh(bh, hkv, sinks, out);
    }
}

extern "C" void kernel_launch(void* const* d_in, const int* in_sizes, int n_in,
                              void* d_out, int out_size) {
    const float* q       = (const float*)d_in[0];
    const float* cmp_kv  = (const float*)d_in[1];
    const float* sinks   = (const float*)d_in[2];
    const int*   cmp_bt  = (const int*)d_in[3];
    const int*   seqused = (const int*)d_in[4];
    const float* ori_kv  = (const float*)d_in[5];
    const int*   ori_bt  = (const int*)d_in[6];
    float* out = (float*)d_out;

    attn_kernel<<<B * HKV * NSPLIT, 256>>>(q, cmp_kv, cmp_bt, seqused,
                                           ori_kv, ori_bt, sinks, out);
}